// round 9
// baseline (speedup 1.0000x reference)
#include <cuda_runtime.h>
#include <cuda_bf16.h>
#include <cstdint>
#include <math.h>

#define BATCH    8192
#define NSITES   256
#define DIM      128
#define NOUT     10
#define TSS      64
#define NTHREADS 256
#define MIDSITES 254
#define VSTRIDE  132

// smem byte offsets
#define OFF_RING 0        // 3 x 64 KB : A half-buffers (ring), each [g][hi/lo][128 l][64 k]
#define OFF_BH   196608   // 16 KB : B_hi [128 k][64 s] bf16, swizzled 128B rows
#define OFF_BL   212992   // 16 KB : B_lo
#define OFF_MB   229376   // 3 mbarriers (8B each)
#define SMEM_TOTAL 229408
#define OFF_V    0        // V [64 s][132 l] fp32 aliases ring slot 0 (final iter only)

__device__ float    g_phiC[NSITES * BATCH];
__device__ float    g_phiS[NSITES * BATCH];
// per site 131072 B: [khalf(2)][g(2)][part hi/lo(2)][l(128)][64 k bf16] swizzled
__device__ uint16_t g_A[(size_t)MIDSITES * 65536];

// ---------------------------------------------------------------------------
// helpers
// ---------------------------------------------------------------------------
__device__ __forceinline__ void split4(float4 f, uint32_t& h01, uint32_t& h23,
                                       uint32_t& l01, uint32_t& l23) {
    asm("cvt.rn.bf16x2.f32 %0, %1, %2;" : "=r"(h01) : "f"(f.y), "f"(f.x));
    asm("cvt.rn.bf16x2.f32 %0, %1, %2;" : "=r"(h23) : "f"(f.w), "f"(f.z));
    const float hx = __uint_as_float(h01 << 16);
    const float hy = __uint_as_float(h01 & 0xffff0000u);
    const float hz = __uint_as_float(h23 << 16);
    const float hw = __uint_as_float(h23 & 0xffff0000u);
    const float lx = f.x - hx, ly = f.y - hy, lz = f.z - hz, lw = f.w - hw;
    asm("cvt.rn.bf16x2.f32 %0, %1, %2;" : "=r"(l01) : "f"(ly), "f"(lx));
    asm("cvt.rn.bf16x2.f32 %0, %1, %2;" : "=r"(l23) : "f"(lw), "f"(lz));
}

__device__ __forceinline__ void split2(float v0, float v1, uint32_t& hh, uint32_t& ll) {
    asm("cvt.rn.bf16x2.f32 %0, %1, %2;" : "=r"(hh) : "f"(v1), "f"(v0));
    const float h0 = __uint_as_float(hh << 16);
    const float h1 = __uint_as_float(hh & 0xffff0000u);
    const float l0 = v0 - h0, l1 = v1 - h1;
    asm("cvt.rn.bf16x2.f32 %0, %1, %2;" : "=r"(ll) : "f"(l1), "f"(l0));
}

__device__ __forceinline__ void ldsm4(uint32_t r[4], uint32_t addr) {
    asm volatile("ldmatrix.sync.aligned.m8n8.x4.shared.b16 {%0,%1,%2,%3}, [%4];"
                 : "=r"(r[0]), "=r"(r[1]), "=r"(r[2]), "=r"(r[3]) : "r"(addr));
}
__device__ __forceinline__ void ldsm4t(uint32_t r[4], uint32_t addr) {
    asm volatile("ldmatrix.sync.aligned.m8n8.x4.trans.shared.b16 {%0,%1,%2,%3}, [%4];"
                 : "=r"(r[0]), "=r"(r[1]), "=r"(r[2]), "=r"(r[3]) : "r"(addr));
}

__device__ __forceinline__ void mma_bf16(float c[4], const uint32_t a[4],
                                         const uint32_t b[2]) {
    asm volatile("mma.sync.aligned.m16n8k16.row.col.f32.bf16.bf16.f32 "
                 "{%0,%1,%2,%3}, {%4,%5,%6,%7}, {%8,%9}, {%0,%1,%2,%3};"
                 : "+f"(c[0]), "+f"(c[1]), "+f"(c[2]), "+f"(c[3])
                 : "r"(a[0]), "r"(a[1]), "r"(a[2]), "r"(a[3]),
                   "r"(b[0]), "r"(b[1]));
}

__device__ __forceinline__ void mma_group(float acc[2][4][4],
        const uint32_t ah0[4], const uint32_t ah1[4],
        const uint32_t al0[4], const uint32_t al1[4],
        const uint32_t bh[4][2], const uint32_t bl[4][2]) {
    #pragma unroll
    for (int ni = 0; ni < 4; ni++) {
        mma_bf16(acc[0][ni], ah0, bh[ni]);
        mma_bf16(acc[1][ni], ah1, bh[ni]);
        mma_bf16(acc[0][ni], al0, bh[ni]);
        mma_bf16(acc[1][ni], al1, bh[ni]);
        mma_bf16(acc[0][ni], ah0, bl[ni]);
        mma_bf16(acc[1][ni], ah1, bl[ni]);
    }
}

#define MBARRIER_INIT(a, c) \
    asm volatile("mbarrier.init.shared.b64 [%0], %1;" \
                 :: "r"((uint32_t)(a)), "r"((uint32_t)(c)) : "memory")
#define MBARRIER_EXPECT_TX(a, n) \
    asm volatile("mbarrier.arrive.expect_tx.shared.b64 _, [%0], %1;" \
                 :: "r"((uint32_t)(a)), "r"((uint32_t)(n)) : "memory")
#define BULK_CP(dst, src, n, mbar) \
    asm volatile("cp.async.bulk.shared::cluster.global.mbarrier::complete_tx::bytes " \
                 "[%0], [%1], %2, [%3];" \
                 :: "r"((uint32_t)(dst)), "l"(src), "r"((uint32_t)(n)), \
                    "r"((uint32_t)(mbar)) : "memory")
#define MBAR_WAIT(mbar, ph) do {                                             \
    uint32_t _m = (uint32_t)(mbar); uint32_t _p = (uint32_t)(ph);            \
    asm volatile("{\n\t.reg .pred P1;\n\t"                                   \
        "WAIT_%=:\n\t"                                                        \
        "mbarrier.try_wait.parity.acquire.cta.shared::cta.b64 P1, [%0], %1, 0x989680;\n\t" \
        "@P1 bra.uni DONE_%=;\n\t"                                            \
        "bra.uni WAIT_%=;\n\t"                                                \
        "DONE_%=:\n\t}" :: "r"(_m), "r"(_p) : "memory");                      \
} while (0)

// ---------------------------------------------------------------------------
// Kernel 0: fused prep — blocks [0,8128) split mid; blocks [8128,16320) phi
// ---------------------------------------------------------------------------
__global__ void prep(const float* __restrict__ x, const float* __restrict__ mid) {
    if (blockIdx.x < 8128) {
        const int gid = blockIdx.x * 256 + threadIdx.x;
        const int site = gid >> 13;
        const int q    = gid & 8191;
        const int l    = q >> 6;
        const int d    = (q >> 5) & 1;
        const int r    = (q & 31) << 2;
        const float4 w = *(const float4*)(mid + (size_t)site * 32768 + l * 256 + d * 128 + r);
        uint32_t h01, h23, l01, l23;
        split4(w, h01, h23, l01, l23);
        const int khalf = r >> 6, rcol = r & 63;
        const size_t base = (size_t)site * 131072 + (size_t)khalf * 65536
                          + (size_t)d * 32768 + (size_t)l * 128
                          + (uint32_t)((((rcol >> 3) ^ (l & 7)) & 7) << 4)
                          + (uint32_t)((r & 7) << 1);
        *(uint2*)((char*)g_A + base)         = make_uint2(h01, h23);
        *(uint2*)((char*)g_A + base + 16384) = make_uint2(l01, l23);
    } else {
        const int b = blockIdx.x - 8128;
        const int n = threadIdx.x;
        const float v = x[b * NSITES + n];
        float mn = v, mx = v;
        #pragma unroll
        for (int off = 16; off > 0; off >>= 1) {
            mn = fminf(mn, __shfl_xor_sync(0xffffffffu, mn, off));
            mx = fmaxf(mx, __shfl_xor_sync(0xffffffffu, mx, off));
        }
        __shared__ float smn[8], smx[8];
        const int w = n >> 5, lane = n & 31;
        if (lane == 0) { smn[w] = mn; smx[w] = mx; }
        __syncthreads();
        mn = smn[0]; mx = smx[0];
        #pragma unroll
        for (int i = 1; i < 8; i++) { mn = fminf(mn, smn[i]); mx = fmaxf(mx, smx[i]); }
        const float ang = 1.57079632679489662f * (v - mn) / (mx - mn + 1e-6f);
        g_phiC[n * BATCH + b] = cosf(ang);
        g_phiS[n * BATCH + b] = sinf(ang);
    }
}

// ---------------------------------------------------------------------------
// Kernel 2: reversed-chain MPS; two GEMMs D0=M0·v, D1=M1·v per site (K=128),
// phi combine fused into fragment epilogue; ring-3 A half-buffer pipeline.
// ---------------------------------------------------------------------------
extern __shared__ char smem_raw[];

__device__ __forceinline__ void do_khalf(
        uint32_t abuf, int kh,
        uint32_t bh0, uint32_t bh1, uint32_t bl0, uint32_t bl1,
        int cA, int r7a,
        float acc0[2][4][4], float acc1[2][4][4]) {
    #pragma unroll
    for (int st = 0; st < 4; st++) {
        const uint32_t kb = (uint32_t)((kh + st * 16) * 128);
        uint32_t q[4];
        uint32_t bh[4][2], bl[4][2];
        ldsm4t(q, bh0 + kb);
        bh[0][0]=q[0]; bh[0][1]=q[1]; bh[1][0]=q[2]; bh[1][1]=q[3];
        ldsm4t(q, bh1 + kb);
        bh[2][0]=q[0]; bh[2][1]=q[1]; bh[3][0]=q[2]; bh[3][1]=q[3];
        ldsm4t(q, bl0 + kb);
        bl[0][0]=q[0]; bl[0][1]=q[1]; bl[1][0]=q[2]; bl[1][1]=q[3];
        ldsm4t(q, bl1 + kb);
        bl[2][0]=q[0]; bl[2][1]=q[1]; bl[3][0]=q[2]; bl[3][1]=q[3];

        const uint32_t tA = (uint32_t)((((2 * st + cA) ^ r7a) & 7) << 4);
        uint32_t ah0[4], ah1[4], al0[4], al1[4];
        ldsm4(ah0, abuf + tA);
        ldsm4(ah1, abuf + tA + 2048);
        ldsm4(al0, abuf + tA + 16384);
        ldsm4(al1, abuf + tA + 18432);
        mma_group(acc0, ah0, ah1, al0, al1, bh, bl);
        ldsm4(ah0, abuf + tA + 32768);
        ldsm4(ah1, abuf + tA + 34816);
        ldsm4(al0, abuf + tA + 49152);
        ldsm4(al1, abuf + tA + 51200);
        mma_group(acc1, ah0, ah1, al0, al1, bh, bl);
    }
}

// source address of half g (g = 2*it + h, site i = 253 - it)
__device__ __forceinline__ const char* half_src(int g) {
    const int site = MIDSITES - 1 - (g >> 1);
    return (const char*)g_A + (size_t)site * 131072 + (size_t)(g & 1) * 65536;
}

__global__ __launch_bounds__(NTHREADS, 1)
void mps_mma(const float* __restrict__ first,
             const float* __restrict__ last,
             const float* __restrict__ wlin,
             const float* __restrict__ blin,
             float* __restrict__ out) {
    const uint32_t sbase = (uint32_t)__cvta_generic_to_shared(smem_raw);
    float* V = (float*)(smem_raw + OFF_V);
    const int tid  = threadIdx.x;
    const int wid  = tid >> 5, lane = tid & 31;
    const int b0   = blockIdx.x * TSS;
    const int wm   = wid & 3, wn = wid >> 2;
    const int m_base = wm * 32, s_base = wn * 32;

    // A ldmatrix lane consts (128B rows)
    const int rowA = m_base + (lane & 15);
    const int cA   = lane >> 4;
    const int r7a  = rowA & 7;
    const uint32_t aoff = (uint32_t)(rowA * 128);

    // B ldmatrix.trans lane consts ([k][s] layout, 128B rows)
    const int mB    = lane >> 3;
    const int kofsB = (mB & 1) * 8 + (lane & 7);
    const int sc0   = s_base + ((mB >> 1) << 3);
    const uint32_t bh0 = sbase + OFF_BH + kofsB * 128
                       + (uint32_t)(((((sc0)      >> 3) ^ (kofsB & 7)) & 7) << 4);
    const uint32_t bh1 = sbase + OFF_BH + kofsB * 128
                       + (uint32_t)(((((sc0 + 16) >> 3) ^ (kofsB & 7)) & 7) << 4);
    const uint32_t bl0 = bh0 + (OFF_BL - OFF_BH);
    const uint32_t bl1 = bh1 + (OFF_BL - OFF_BH);

    // epilogue lane consts
    const int rr = lane >> 2, cq = (lane & 3) * 2;
    const int snib = s_base >> 3;

    if (tid < 3) MBARRIER_INIT(sbase + OFF_MB + tid * 8, 1);
    __syncthreads();

    // prologue: fill ring slots 0..2 with halves g=0,1,2
    if (tid == 0) {
        #pragma unroll
        for (int g = 0; g < 3; g++) {
            MBARRIER_EXPECT_TX(sbase + OFF_MB + g * 8, 65536);
            BULK_CP(sbase + OFF_RING + g * 65536, half_src(g), 65536,
                    sbase + OFF_MB + g * 8);
        }
    }

    // initial B = R_254[r] = last[r,0]*c255 + last[r,1]*s255 (unscaled)
    {
        __shared__ float phiL[128];
        if (tid < 64)        phiL[tid] = g_phiC[(size_t)(NSITES - 1) * BATCH + b0 + tid];
        else if (tid < 128)  phiL[tid] = g_phiS[(size_t)(NSITES - 1) * BATCH + b0 + tid - 64];
        __syncthreads();
        const int r = tid >> 1;
        const int sblk = (tid & 1) * 32;
        const float l0 = last[2 * r], l1 = last[2 * r + 1];
        for (int s = sblk; s < sblk + 32; s += 2) {
            const float v0 = l0 * phiL[s]     + l1 * phiL[64 + s];
            const float v1 = l0 * phiL[s + 1] + l1 * phiL[64 + s + 1];
            uint32_t hh, ll;
            split2(v0, v1, hh, ll);
            const uint32_t o = (uint32_t)(r * 128)
                             + (uint32_t)((((s >> 3) ^ (r & 7)) & 7) << 4)
                             + (uint32_t)((s & 7) << 1);
            *(uint32_t*)(smem_raw + OFF_BH + o) = hh;
            *(uint32_t*)(smem_raw + OFF_BL + o) = ll;
        }
    }
    __syncthreads();

    for (int it = 0; it < MIDSITES; ++it) {
        const int i = MIDSITES - 1 - it;          // mid index
        const bool last_it = (it == MIDSITES - 1);
        const int g0 = 2 * it, g1 = g0 + 1;

        // prefetch phi[site i+1] for the epilogue combine
        float2 pc[4], ps[4];
        {
            const size_t pb = (size_t)(i + 1) * BATCH + b0 + s_base + cq;
            #pragma unroll
            for (int ni = 0; ni < 4; ni++) {
                pc[ni] = *(const float2*)&g_phiC[pb + 8 * ni];
                ps[ni] = *(const float2*)&g_phiS[pb + 8 * ni];
            }
        }

        float acc0[2][4][4], acc1[2][4][4];
        #pragma unroll
        for (int mi = 0; mi < 2; mi++)
            #pragma unroll
            for (int ni = 0; ni < 4; ni++)
                #pragma unroll
                for (int e = 0; e < 4; e++) { acc0[mi][ni][e] = 0.0f; acc1[mi][ni][e] = 0.0f; }

        // ===== k-half 0 =====
        {
            const int slot = g0 % 3;
            MBAR_WAIT(sbase + OFF_MB + slot * 8, (g0 / 3) & 1);
            do_khalf(sbase + OFF_RING + slot * 65536 + aoff, 0,
                     bh0, bh1, bl0, bl1, cA, r7a, acc0, acc1);
            __syncthreads();
            if (g0 + 3 <= 2 * MIDSITES - 1 && tid == 0) {
                MBARRIER_EXPECT_TX(sbase + OFF_MB + slot * 8, 65536);
                BULK_CP(sbase + OFF_RING + slot * 65536, half_src(g0 + 3), 65536,
                        sbase + OFF_MB + slot * 8);
            }
        }
        // ===== k-half 1 =====
        {
            const int slot = g1 % 3;
            MBAR_WAIT(sbase + OFF_MB + slot * 8, (g1 / 3) & 1);
            do_khalf(sbase + OFF_RING + slot * 65536 + aoff, 64,
                     bh0, bh1, bl0, bl1, cA, r7a, acc0, acc1);
            __syncthreads();   // A slot + B reads done
            if (g1 + 3 <= 2 * MIDSITES - 1 && tid == 0) {
                MBARRIER_EXPECT_TX(sbase + OFF_MB + slot * 8, 65536);
                BULK_CP(sbase + OFF_RING + slot * 65536, half_src(g1 + 3), 65536,
                        sbase + OFF_MB + slot * 8);
            }
        }

        // ===== fused epilogue: right = c*D0 + s*D1 -> next B (or V) =====
        if (!last_it) {
            #pragma unroll
            for (int ni = 0; ni < 4; ni++) {
                const float cx = pc[ni].x, cy = pc[ni].y;
                const float sx = ps[ni].x, sy = ps[ni].y;
                const uint32_t chs = (uint32_t)((((snib + ni) ^ rr) & 7) << 4)
                                   + (uint32_t)(cq << 1);
                #pragma unroll
                for (int mi = 0; mi < 2; mi++) {
                    const int r = m_base + 16 * mi + rr;
                    const float v0 = cx * acc0[mi][ni][0] + sx * acc1[mi][ni][0];
                    const float v1 = cy * acc0[mi][ni][1] + sy * acc1[mi][ni][1];
                    const float v2 = cx * acc0[mi][ni][2] + sx * acc1[mi][ni][2];
                    const float v3 = cy * acc0[mi][ni][3] + sy * acc1[mi][ni][3];
                    uint32_t hh, ll;
                    const uint32_t o = (uint32_t)(r * 128) + chs;
                    split2(v0, v1, hh, ll);
                    *(uint32_t*)(smem_raw + OFF_BH + o) = hh;
                    *(uint32_t*)(smem_raw + OFF_BL + o) = ll;
                    split2(v2, v3, hh, ll);
                    *(uint32_t*)(smem_raw + OFF_BH + o + 1024) = hh;
                    *(uint32_t*)(smem_raw + OFF_BL + o + 1024) = ll;
                }
            }
        } else {
            #pragma unroll
            for (int ni = 0; ni < 4; ni++) {
                const float cx = pc[ni].x, cy = pc[ni].y;
                const float sx = ps[ni].x, sy = ps[ni].y;
                const int s = s_base + 8 * ni + cq;
                #pragma unroll
                for (int mi = 0; mi < 2; mi++) {
                    const int r = m_base + 16 * mi + rr;
                    V[s * VSTRIDE + r]           = cx * acc0[mi][ni][0] + sx * acc1[mi][ni][0];
                    V[(s + 1) * VSTRIDE + r]     = cy * acc0[mi][ni][1] + sy * acc1[mi][ni][1];
                    V[s * VSTRIDE + r + 8]       = cx * acc0[mi][ni][2] + sx * acc1[mi][ni][2];
                    V[(s + 1) * VSTRIDE + r + 8] = cy * acc0[mi][ni][3] + sy * acc1[mi][ni][3];
                }
            }
        }
        __syncthreads();
    }

    // final head: scalar_s = sum_r (first[0][r]c0 + first[1][r]s0) * R_0[r]
    if (tid < TSS) {
        const int s = tid;
        const float c0 = g_phiC[b0 + s];
        const float s0 = g_phiS[b0 + s];
        float accs = 0.0f;
        #pragma unroll 4
        for (int l = 0; l < DIM; l++) {
            const float lv = fmaf(first[l], c0, first[DIM + l] * s0);
            accs = fmaf(lv, V[s * VSTRIDE + l], accs);
        }
        #pragma unroll
        for (int o = 0; o < NOUT; o++)
            out[(b0 + s) * NOUT + o] = fmaf(accs, wlin[o], blin[o]);
    }
}

// ---------------------------------------------------------------------------
extern "C" void kernel_launch(void* const* d_in, const int* in_sizes, int n_in,
                              void* d_out, int out_size) {
    const float* x     = (const float*)d_in[0];
    const float* first = (const float*)d_in[1];
    const float* mid   = (const float*)d_in[2];
    const float* last  = (const float*)d_in[3];
    const float* wlin  = (const float*)d_in[4];
    const float* blin  = (const float*)d_in[5];
    float* out = (float*)d_out;

    cudaFuncSetAttribute(mps_mma, cudaFuncAttributeMaxDynamicSharedMemorySize,
                         SMEM_TOTAL);

    prep<<<16320, 256>>>(x, mid);
    mps_mma<<<BATCH / TSS, NTHREADS, SMEM_TOTAL>>>(first, last, wlin, blin, out);
}

// round 10
// speedup vs baseline: 1.1118x; 1.1118x over previous
#include <cuda_runtime.h>
#include <cuda_bf16.h>
#include <cstdint>
#include <math.h>

#define BATCH    8192
#define NSITES   256
#define DIM      128
#define NOUT     10
#define TSS      64
#define NTHREADS 256
#define MIDSITES 254

// smem byte offsets
#define OFF_RING 0        // 3 x 64 KB : shared A half-buffers (ring)
#define OFF_BH   196608   // [grp0 Bh 8K][grp1 Bh 8K][grp0 Bl 8K][grp1 Bl 8K]
#define OFF_MB   229376   // full[3] @+0, empty[3] @+24, stagger @+48
#define SMEM_TOTAL 229440

__device__ float    g_phiC[NSITES * BATCH];
__device__ float    g_phiS[NSITES * BATCH];
// per site 131072 B: [khalf(2)][g(2)][hi/lo(2)][l(128)][64 k bf16] swizzled
__device__ uint16_t g_A[(size_t)MIDSITES * 65536];

// ---------------------------------------------------------------------------
__device__ __forceinline__ void split4(float4 f, uint32_t& h01, uint32_t& h23,
                                       uint32_t& l01, uint32_t& l23) {
    asm("cvt.rn.bf16x2.f32 %0, %1, %2;" : "=r"(h01) : "f"(f.y), "f"(f.x));
    asm("cvt.rn.bf16x2.f32 %0, %1, %2;" : "=r"(h23) : "f"(f.w), "f"(f.z));
    const float hx = __uint_as_float(h01 << 16);
    const float hy = __uint_as_float(h01 & 0xffff0000u);
    const float hz = __uint_as_float(h23 << 16);
    const float hw = __uint_as_float(h23 & 0xffff0000u);
    const float lx = f.x - hx, ly = f.y - hy, lz = f.z - hz, lw = f.w - hw;
    asm("cvt.rn.bf16x2.f32 %0, %1, %2;" : "=r"(l01) : "f"(ly), "f"(lx));
    asm("cvt.rn.bf16x2.f32 %0, %1, %2;" : "=r"(l23) : "f"(lw), "f"(lz));
}

__device__ __forceinline__ void split2(float v0, float v1, uint32_t& hh, uint32_t& ll) {
    asm("cvt.rn.bf16x2.f32 %0, %1, %2;" : "=r"(hh) : "f"(v1), "f"(v0));
    const float h0 = __uint_as_float(hh << 16);
    const float h1 = __uint_as_float(hh & 0xffff0000u);
    const float l0 = v0 - h0, l1 = v1 - h1;
    asm("cvt.rn.bf16x2.f32 %0, %1, %2;" : "=r"(ll) : "f"(l1), "f"(l0));
}

__device__ __forceinline__ void ldsm4(uint32_t r[4], uint32_t addr) {
    asm volatile("ldmatrix.sync.aligned.m8n8.x4.shared.b16 {%0,%1,%2,%3}, [%4];"
                 : "=r"(r[0]), "=r"(r[1]), "=r"(r[2]), "=r"(r[3]) : "r"(addr));
}
__device__ __forceinline__ void ldsm4t(uint32_t r[4], uint32_t addr) {
    asm volatile("ldmatrix.sync.aligned.m8n8.x4.trans.shared.b16 {%0,%1,%2,%3}, [%4];"
                 : "=r"(r[0]), "=r"(r[1]), "=r"(r[2]), "=r"(r[3]) : "r"(addr));
}

__device__ __forceinline__ void mma_bf16(float c[4], const uint32_t a[4],
                                         const uint32_t b[2]) {
    asm volatile("mma.sync.aligned.m16n8k16.row.col.f32.bf16.bf16.f32 "
                 "{%0,%1,%2,%3}, {%4,%5,%6,%7}, {%8,%9}, {%0,%1,%2,%3};"
                 : "+f"(c[0]), "+f"(c[1]), "+f"(c[2]), "+f"(c[3])
                 : "r"(a[0]), "r"(a[1]), "r"(a[2]), "r"(a[3]),
                   "r"(b[0]), "r"(b[1]));
}

__device__ __forceinline__ void mma_group(float acc[2][4][4],
        const uint32_t ah0[4], const uint32_t ah1[4],
        const uint32_t al0[4], const uint32_t al1[4],
        const uint32_t bh[4][2], const uint32_t bl[4][2]) {
    #pragma unroll
    for (int ni = 0; ni < 4; ni++) {
        mma_bf16(acc[0][ni], ah0, bh[ni]);
        mma_bf16(acc[1][ni], ah1, bh[ni]);
        mma_bf16(acc[0][ni], al0, bh[ni]);
        mma_bf16(acc[1][ni], al1, bh[ni]);
        mma_bf16(acc[0][ni], ah0, bl[ni]);
        mma_bf16(acc[1][ni], ah1, bl[ni]);
    }
}

#define MBARRIER_INIT(a, c) \
    asm volatile("mbarrier.init.shared.b64 [%0], %1;" \
                 :: "r"((uint32_t)(a)), "r"((uint32_t)(c)) : "memory")
#define MBARRIER_ARRIVE(a) \
    asm volatile("mbarrier.arrive.shared.b64 _, [%0];" \
                 :: "r"((uint32_t)(a)) : "memory")
#define MBARRIER_EXPECT_TX(a, n) \
    asm volatile("mbarrier.arrive.expect_tx.shared.b64 _, [%0], %1;" \
                 :: "r"((uint32_t)(a)), "r"((uint32_t)(n)) : "memory")
#define BULK_CP(dst, src, n, mbar) \
    asm volatile("cp.async.bulk.shared::cluster.global.mbarrier::complete_tx::bytes " \
                 "[%0], [%1], %2, [%3];" \
                 :: "r"((uint32_t)(dst)), "l"(src), "r"((uint32_t)(n)), \
                    "r"((uint32_t)(mbar)) : "memory")
#define MBAR_WAIT(mbar, ph) do {                                             \
    uint32_t _m = (uint32_t)(mbar); uint32_t _p = (uint32_t)(ph);            \
    asm volatile("{\n\t.reg .pred P1;\n\t"                                   \
        "WAIT_%=:\n\t"                                                        \
        "mbarrier.try_wait.parity.acquire.cta.shared::cta.b64 P1, [%0], %1, 0x989680;\n\t" \
        "@P1 bra.uni DONE_%=;\n\t"                                            \
        "bra.uni WAIT_%=;\n\t"                                                \
        "DONE_%=:\n\t}" :: "r"(_m), "r"(_p) : "memory");                      \
} while (0)
#define BARG() asm volatile("bar.sync %0, 128;" :: "r"(1 + grp) : "memory")

// ---------------------------------------------------------------------------
// Kernel 0: fused prep — blocks [0,8128) split mid; blocks [8128,16320) phi
// ---------------------------------------------------------------------------
__global__ void prep(const float* __restrict__ x, const float* __restrict__ mid) {
    if (blockIdx.x < 8128) {
        const int gid = blockIdx.x * 256 + threadIdx.x;
        const int site = gid >> 13;
        const int q    = gid & 8191;
        const int l    = q >> 6;
        const int d    = (q >> 5) & 1;
        const int r    = (q & 31) << 2;
        const float4 w = *(const float4*)(mid + (size_t)site * 32768 + l * 256 + d * 128 + r);
        uint32_t h01, h23, l01, l23;
        split4(w, h01, h23, l01, l23);
        const int khalf = r >> 6, rcol = r & 63;
        const size_t base = (size_t)site * 131072 + (size_t)khalf * 65536
                          + (size_t)d * 32768 + (size_t)l * 128
                          + (uint32_t)((((rcol >> 3) ^ (l & 7)) & 7) << 4)
                          + (uint32_t)((r & 7) << 1);
        *(uint2*)((char*)g_A + base)         = make_uint2(h01, h23);
        *(uint2*)((char*)g_A + base + 16384) = make_uint2(l01, l23);
    } else {
        const int b = blockIdx.x - 8128;
        const int n = threadIdx.x;
        const float v = x[b * NSITES + n];
        float mn = v, mx = v;
        #pragma unroll
        for (int off = 16; off > 0; off >>= 1) {
            mn = fminf(mn, __shfl_xor_sync(0xffffffffu, mn, off));
            mx = fmaxf(mx, __shfl_xor_sync(0xffffffffu, mx, off));
        }
        __shared__ float smn[8], smx[8];
        const int w = n >> 5, lane = n & 31;
        if (lane == 0) { smn[w] = mn; smx[w] = mx; }
        __syncthreads();
        mn = smn[0]; mx = smx[0];
        #pragma unroll
        for (int i = 1; i < 8; i++) { mn = fminf(mn, smn[i]); mx = fmaxf(mx, smx[i]); }
        const float ang = 1.57079632679489662f * (v - mn) / (mx - mn + 1e-6f);
        g_phiC[n * BATCH + b] = cosf(ang);
        g_phiS[n * BATCH + b] = sinf(ang);
    }
}

// ---------------------------------------------------------------------------
// Kernel 2: two independent 32-sample chains per CTA (warps 0-3 / 4-7),
// free-running with shared A ring so one group's MMA hides the other's epilogue.
// ---------------------------------------------------------------------------
extern __shared__ char smem_raw[];

__device__ __forceinline__ const char* half_src(int g) {
    const int site = MIDSITES - 1 - (g >> 1);
    return (const char*)g_A + (size_t)site * 131072 + (size_t)(g & 1) * 65536;
}

__device__ __forceinline__ void do_khalf(
        uint32_t abuf, int kh, uint32_t bh0, uint32_t bh1,
        int cA, int r7a, float acc0[2][4][4], float acc1[2][4][4]) {
    #pragma unroll
    for (int st = 0; st < 4; st++) {
        const uint32_t kb = (uint32_t)((kh + st * 16) * 64);
        uint32_t q[4];
        uint32_t bh[4][2], bl[4][2];
        ldsm4t(q, bh0 + kb);
        bh[0][0]=q[0]; bh[0][1]=q[1]; bh[1][0]=q[2]; bh[1][1]=q[3];
        ldsm4t(q, bh1 + kb);
        bh[2][0]=q[0]; bh[2][1]=q[1]; bh[3][0]=q[2]; bh[3][1]=q[3];
        ldsm4t(q, bh0 + kb + 16384);
        bl[0][0]=q[0]; bl[0][1]=q[1]; bl[1][0]=q[2]; bl[1][1]=q[3];
        ldsm4t(q, bh1 + kb + 16384);
        bl[2][0]=q[0]; bl[2][1]=q[1]; bl[3][0]=q[2]; bl[3][1]=q[3];

        const uint32_t tA = (uint32_t)((((2 * st + cA) ^ r7a) & 7) << 4);
        uint32_t ah0[4], ah1[4], al0[4], al1[4];
        ldsm4(ah0, abuf + tA);
        ldsm4(ah1, abuf + tA + 2048);
        ldsm4(al0, abuf + tA + 16384);
        ldsm4(al1, abuf + tA + 18432);
        mma_group(acc0, ah0, ah1, al0, al1, bh, bl);
        ldsm4(ah0, abuf + tA + 32768);
        ldsm4(ah1, abuf + tA + 34816);
        ldsm4(al0, abuf + tA + 49152);
        ldsm4(al1, abuf + tA + 51200);
        mma_group(acc1, ah0, ah1, al0, al1, bh, bl);
    }
}

__global__ __launch_bounds__(NTHREADS, 1)
void mps_mma(const float* __restrict__ first,
             const float* __restrict__ last,
             const float* __restrict__ wlin,
             const float* __restrict__ blin,
             float* __restrict__ out) {
    const uint32_t sbase = (uint32_t)__cvta_generic_to_shared(smem_raw);
    const int tid  = threadIdx.x;
    const int wid  = tid >> 5, lane = tid & 31;
    const int grp  = wid >> 2;                 // 0: samples 0-31, 1: 32-63
    const int wm   = wid & 3;
    const int b0   = blockIdx.x * TSS;
    const int m_base = wm * 32;

    // A ldmatrix lane consts
    const int rowA = m_base + (lane & 15);
    const int cA   = lane >> 4;
    const int r7a  = rowA & 7;
    const uint32_t aoff = (uint32_t)(rowA * 128);

    // B ldmatrix.trans lane consts ([k 128][32 s] per group, 64B rows)
    const uint32_t grpB = sbase + OFF_BH + grp * 8192;
    const int kofsB = lane & 15;
    const int sg8   = (lane >> 4) << 3;        // 0 or 8
    const int chm   = (kofsB >> 1) & 3;
    const uint32_t bh0 = grpB + kofsB * 64 + (uint32_t)((((sg8 >> 3)       ^ chm) & 3) << 4);
    const uint32_t bh1 = grpB + kofsB * 64 + (uint32_t)(((((16 + sg8) >> 3) ^ chm) & 3) << 4);

    // epilogue lane consts
    const int rr = lane >> 2, cq = (lane & 3) * 2;
    char* gBh = smem_raw + OFF_BH + grp * 8192;
    char* gBl = gBh + 16384;

    const uint32_t fullb  = sbase + OFF_MB;
    const uint32_t emptyb = sbase + OFF_MB + 24;
    const uint32_t stgb   = sbase + OFF_MB + 48;

    if (tid < 3)        MBARRIER_INIT(fullb + tid * 8, 1);
    else if (tid < 6)   MBARRIER_INIT(emptyb + (tid - 3) * 8, 2);
    else if (tid == 6)  MBARRIER_INIT(stgb, 1);
    __syncthreads();

    if (tid == 0) {
        #pragma unroll
        for (int g = 0; g < 3; g++) {
            MBARRIER_EXPECT_TX(fullb + g * 8, 65536);
            BULK_CP(sbase + OFF_RING + g * 65536, half_src(g), 65536, fullb + g * 8);
        }
    }

    // initial B = last ⊙ phi[255] (per group, [k=r][s])
    {
        const int g_ = tid >> 7, r = tid & 127;
        char* bh_ = smem_raw + OFF_BH + g_ * 8192;
        char* bl_ = bh_ + 16384;
        const float l0 = last[2 * r], l1 = last[2 * r + 1];
        const float* pC = g_phiC + (size_t)(NSITES - 1) * BATCH + b0 + g_ * 32;
        const float* pS = g_phiS + (size_t)(NSITES - 1) * BATCH + b0 + g_ * 32;
        const int cm = (r >> 1) & 3;
        #pragma unroll
        for (int s = 0; s < 32; s += 2) {
            const float v0 = l0 * pC[s]     + l1 * pS[s];
            const float v1 = l0 * pC[s + 1] + l1 * pS[s + 1];
            uint32_t hh, ll;
            split2(v0, v1, hh, ll);
            const uint32_t o = (uint32_t)(r * 64 + ((((s >> 3) ^ cm) & 3) << 4)
                                          + ((s & 7) << 1));
            *(uint32_t*)(bh_ + o) = hh;
            *(uint32_t*)(bl_ + o) = ll;
        }
    }
    __syncthreads();

    if (grp == 1) MBAR_WAIT(stgb, 0);     // stagger: G1 starts after G0's first k-half

    for (int it = 0; it < MIDSITES; ++it) {
        const int i = MIDSITES - 1 - it;
        const bool last_it = (it == MIDSITES - 1);

        // prefetch phi[site i+1] (epilogue combine)
        float2 pc[4], ps[4];
        {
            const size_t pb = (size_t)(i + 1) * BATCH + b0 + grp * 32 + cq;
            #pragma unroll
            for (int ni = 0; ni < 4; ni++) {
                pc[ni] = *(const float2*)&g_phiC[pb + 8 * ni];
                ps[ni] = *(const float2*)&g_phiS[pb + 8 * ni];
            }
        }

        float acc0[2][4][4], acc1[2][4][4];
        #pragma unroll
        for (int mi = 0; mi < 2; mi++)
            #pragma unroll
            for (int ni = 0; ni < 4; ni++)
                #pragma unroll
                for (int e = 0; e < 4; e++) { acc0[mi][ni][e] = 0.0f; acc1[mi][ni][e] = 0.0f; }

        #pragma unroll
        for (int h = 0; h < 2; h++) {
            const int g    = 2 * it + h;
            const int slot = g % 3;
            const int par  = (g / 3) & 1;
            MBAR_WAIT(fullb + slot * 8, par);
            do_khalf(sbase + OFF_RING + slot * 65536 + aoff, h * 64,
                     bh0, bh1, cA, r7a, acc0, acc1);
            BARG();
            if ((tid & 127) == 0) {
                MBARRIER_ARRIVE(emptyb + slot * 8);
                if (grp == 1 && g < 505) {        // lagging group refills
                    MBAR_WAIT(emptyb + slot * 8, par);
                    MBARRIER_EXPECT_TX(fullb + slot * 8, 65536);
                    BULK_CP(sbase + OFF_RING + slot * 65536, half_src(g + 3),
                            65536, fullb + slot * 8);
                }
            }
            if (it == 0 && h == 0 && tid == 0) MBARRIER_ARRIVE(stgb);
        }

        if (!last_it) {
            // fused epilogue: right = c*D0 + s*D1 -> own next B (k-major)
            #pragma unroll
            for (int ni = 0; ni < 4; ni++) {
                const float cx = pc[ni].x, cy = pc[ni].y;
                const float sx = ps[ni].x, sy = ps[ni].y;
                #pragma unroll
                for (int mi = 0; mi < 2; mi++) {
                    const int r = m_base + 16 * mi + rr;
                    const float v0 = cx * acc0[mi][ni][0] + sx * acc1[mi][ni][0];
                    const float v1 = cy * acc0[mi][ni][1] + sy * acc1[mi][ni][1];
                    const float v2 = cx * acc0[mi][ni][2] + sx * acc1[mi][ni][2];
                    const float v3 = cy * acc0[mi][ni][3] + sy * acc1[mi][ni][3];
                    const uint32_t o = (uint32_t)(r * 64
                                     + (((ni ^ ((r >> 1) & 3)) & 3) << 4) + (cq << 1));
                    uint32_t hh, ll;
                    split2(v0, v1, hh, ll);
                    *(uint32_t*)(gBh + o) = hh;
                    *(uint32_t*)(gBl + o) = ll;
                    split2(v2, v3, hh, ll);
                    *(uint32_t*)(gBh + o + 512) = hh;   // r+8: same chunk, +8 rows
                    *(uint32_t*)(gBl + o + 512) = ll;
                }
            }
            BARG();   // own B ready for next site
        } else {
            // final head from fragments: scalar_s = sum_l L0(l,s) * right0(l,s)
            float2 c0v[4], s0v[4];
            const size_t hb = (size_t)b0 + grp * 32 + cq;
            #pragma unroll
            for (int ni = 0; ni < 4; ni++) {
                c0v[ni] = *(const float2*)&g_phiC[hb + 8 * ni];
                s0v[ni] = *(const float2*)&g_phiS[hb + 8 * ni];
            }
            float fA[2][2], fB[2][2];
            #pragma unroll
            for (int mi = 0; mi < 2; mi++) {
                const int l0 = m_base + 16 * mi + rr;
                fA[mi][0] = first[l0];      fB[mi][0] = first[DIM + l0];
                fA[mi][1] = first[l0 + 8];  fB[mi][1] = first[DIM + l0 + 8];
            }
            float* scr = (float*)gBh;   // B dead after final MMA
            #pragma unroll
            for (int ni = 0; ni < 4; ni++) {
                float pe = 0.f, po = 0.f;
                const float cx = pc[ni].x, cy = pc[ni].y;
                const float sx = ps[ni].x, sy = ps[ni].y;
                const float Lc0 = c0v[ni].x, Lc1 = c0v[ni].y;
                const float Ls0 = s0v[ni].x, Ls1 = s0v[ni].y;
                #pragma unroll
                for (int mi = 0; mi < 2; mi++) {
                    const float r0 = cx * acc0[mi][ni][0] + sx * acc1[mi][ni][0];
                    const float r1 = cy * acc0[mi][ni][1] + sy * acc1[mi][ni][1];
                    const float r2 = cx * acc0[mi][ni][2] + sx * acc1[mi][ni][2];
                    const float r3 = cy * acc0[mi][ni][3] + sy * acc1[mi][ni][3];
                    const float L0e = fA[mi][0] * Lc0 + fB[mi][0] * Ls0;
                    const float L0o = fA[mi][0] * Lc1 + fB[mi][0] * Ls1;
                    const float L1e = fA[mi][1] * Lc0 + fB[mi][1] * Ls0;
                    const float L1o = fA[mi][1] * Lc1 + fB[mi][1] * Ls1;
                    pe += L0e * r0 + L1e * r2;
                    po += L0o * r1 + L1o * r3;
                }
                #pragma unroll
                for (int m = 4; m <= 16; m <<= 1) {
                    pe += __shfl_xor_sync(0xffffffffu, pe, m);
                    po += __shfl_xor_sync(0xffffffffu, po, m);
                }
                if (lane < 4) {
                    scr[wm * 32 + 8 * ni + cq]     = pe;
                    scr[wm * 32 + 8 * ni + cq + 1] = po;
                }
            }
            BARG();
            const int gt = tid & 127;
            if (gt < 32) {
                const float sc = scr[gt] + scr[32 + gt] + scr[64 + gt] + scr[96 + gt];
                const int samp = b0 + grp * 32 + gt;
                #pragma unroll
                for (int o = 0; o < NOUT; o++)
                    out[samp * NOUT + o] = fmaf(sc, wlin[o], blin[o]);
            }
        }
    }
}

// ---------------------------------------------------------------------------
extern "C" void kernel_launch(void* const* d_in, const int* in_sizes, int n_in,
                              void* d_out, int out_size) {
    const float* x     = (const float*)d_in[0];
    const float* first = (const float*)d_in[1];
    const float* mid   = (const float*)d_in[2];
    const float* last  = (const float*)d_in[3];
    const float* wlin  = (const float*)d_in[4];
    const float* blin  = (const float*)d_in[5];
    float* out = (float*)d_out;

    cudaFuncSetAttribute(mps_mma, cudaFuncAttributeMaxDynamicSharedMemorySize,
                         SMEM_TOTAL);

    prep<<<16320, 256>>>(x, mid);
    mps_mma<<<BATCH / TSS, NTHREADS, SMEM_TOTAL>>>(first, last, wlin, blin, out);
}

// round 11
// speedup vs baseline: 1.1146x; 1.0025x over previous
#include <cuda_runtime.h>
#include <cuda_bf16.h>
#include <cstdint>
#include <math.h>

#define BATCH    8192
#define NSITES   256
#define DIM      128
#define NOUT     10
#define TSS      64
#define NTHREADS 256
#define MIDSITES 254

// smem byte offsets
#define OFF_RING 0        // 3 x 64 KB : shared A half-buffers (ring)
#define OFF_BH   196608   // [grp0 Bh 8K][grp1 Bh 8K][grp0 Bl 8K][grp1 Bl 8K]
#define OFF_MB   229376   // full[3] @+0, empty[3] @+24, stagger @+48
#define SMEM_TOTAL 229440

__device__ float    g_phiC[NSITES * BATCH];
__device__ float    g_phiS[NSITES * BATCH];
// per site 131072 B: [khalf(2)][g(2)][hi/lo(2)][l(128)][64 k bf16] swizzled
__device__ uint16_t g_A[(size_t)MIDSITES * 65536];

// ---------------------------------------------------------------------------
__device__ __forceinline__ void split4(float4 f, uint32_t& h01, uint32_t& h23,
                                       uint32_t& l01, uint32_t& l23) {
    asm("cvt.rn.bf16x2.f32 %0, %1, %2;" : "=r"(h01) : "f"(f.y), "f"(f.x));
    asm("cvt.rn.bf16x2.f32 %0, %1, %2;" : "=r"(h23) : "f"(f.w), "f"(f.z));
    const float hx = __uint_as_float(h01 << 16);
    const float hy = __uint_as_float(h01 & 0xffff0000u);
    const float hz = __uint_as_float(h23 << 16);
    const float hw = __uint_as_float(h23 & 0xffff0000u);
    const float lx = f.x - hx, ly = f.y - hy, lz = f.z - hz, lw = f.w - hw;
    asm("cvt.rn.bf16x2.f32 %0, %1, %2;" : "=r"(l01) : "f"(ly), "f"(lx));
    asm("cvt.rn.bf16x2.f32 %0, %1, %2;" : "=r"(l23) : "f"(lw), "f"(lz));
}

__device__ __forceinline__ void split2(float v0, float v1, uint32_t& hh, uint32_t& ll) {
    asm("cvt.rn.bf16x2.f32 %0, %1, %2;" : "=r"(hh) : "f"(v1), "f"(v0));
    const float h0 = __uint_as_float(hh << 16);
    const float h1 = __uint_as_float(hh & 0xffff0000u);
    const float l0 = v0 - h0, l1 = v1 - h1;
    asm("cvt.rn.bf16x2.f32 %0, %1, %2;" : "=r"(ll) : "f"(l1), "f"(l0));
}

__device__ __forceinline__ void ldsm4(uint32_t r[4], uint32_t addr) {
    asm volatile("ldmatrix.sync.aligned.m8n8.x4.shared.b16 {%0,%1,%2,%3}, [%4];"
                 : "=r"(r[0]), "=r"(r[1]), "=r"(r[2]), "=r"(r[3]) : "r"(addr));
}
__device__ __forceinline__ void ldsm4t(uint32_t r[4], uint32_t addr) {
    asm volatile("ldmatrix.sync.aligned.m8n8.x4.trans.shared.b16 {%0,%1,%2,%3}, [%4];"
                 : "=r"(r[0]), "=r"(r[1]), "=r"(r[2]), "=r"(r[3]) : "r"(addr));
}

__device__ __forceinline__ void mma_bf16(float c[4], const uint32_t a[4],
                                         const uint32_t b[2]) {
    asm volatile("mma.sync.aligned.m16n8k16.row.col.f32.bf16.bf16.f32 "
                 "{%0,%1,%2,%3}, {%4,%5,%6,%7}, {%8,%9}, {%0,%1,%2,%3};"
                 : "+f"(c[0]), "+f"(c[1]), "+f"(c[2]), "+f"(c[3])
                 : "r"(a[0]), "r"(a[1]), "r"(a[2]), "r"(a[3]),
                   "r"(b[0]), "r"(b[1]));
}

__device__ __forceinline__ void mma_group(float acc[2][4][4],
        const uint32_t ah0[4], const uint32_t ah1[4],
        const uint32_t al0[4], const uint32_t al1[4],
        const uint32_t bh[4][2], const uint32_t bl[4][2]) {
    #pragma unroll
    for (int ni = 0; ni < 4; ni++) {
        mma_bf16(acc[0][ni], ah0, bh[ni]);
        mma_bf16(acc[1][ni], ah1, bh[ni]);
        mma_bf16(acc[0][ni], al0, bh[ni]);
        mma_bf16(acc[1][ni], al1, bh[ni]);
        mma_bf16(acc[0][ni], ah0, bl[ni]);
        mma_bf16(acc[1][ni], ah1, bl[ni]);
    }
}

#define MBARRIER_INIT(a, c) \
    asm volatile("mbarrier.init.shared.b64 [%0], %1;" \
                 :: "r"((uint32_t)(a)), "r"((uint32_t)(c)) : "memory")
#define MBARRIER_ARRIVE(a) \
    asm volatile("mbarrier.arrive.shared.b64 _, [%0];" \
                 :: "r"((uint32_t)(a)) : "memory")
#define MBARRIER_EXPECT_TX(a, n) \
    asm volatile("mbarrier.arrive.expect_tx.shared.b64 _, [%0], %1;" \
                 :: "r"((uint32_t)(a)), "r"((uint32_t)(n)) : "memory")
#define BULK_CP(dst, src, n, mbar) \
    asm volatile("cp.async.bulk.shared::cluster.global.mbarrier::complete_tx::bytes " \
                 "[%0], [%1], %2, [%3];" \
                 :: "r"((uint32_t)(dst)), "l"(src), "r"((uint32_t)(n)), \
                    "r"((uint32_t)(mbar)) : "memory")
#define MBAR_WAIT(mbar, ph) do {                                             \
    uint32_t _m = (uint32_t)(mbar); uint32_t _p = (uint32_t)(ph);            \
    asm volatile("{\n\t.reg .pred P1;\n\t"                                   \
        "WAIT_%=:\n\t"                                                        \
        "mbarrier.try_wait.parity.acquire.cta.shared::cta.b64 P1, [%0], %1, 0x989680;\n\t" \
        "@P1 bra.uni DONE_%=;\n\t"                                            \
        "bra.uni WAIT_%=;\n\t"                                                \
        "DONE_%=:\n\t}" :: "r"(_m), "r"(_p) : "memory");                      \
} while (0)
#define BARG() asm volatile("bar.sync %0, 128;" :: "r"(1 + grp) : "memory")

// ---------------------------------------------------------------------------
// Kernel 0: fused prep — blocks [0,8128) split mid; blocks [8128,16320) phi
// ---------------------------------------------------------------------------
__global__ void prep(const float* __restrict__ x, const float* __restrict__ mid) {
    if (blockIdx.x < 8128) {
        const int gid = blockIdx.x * 256 + threadIdx.x;
        const int site = gid >> 13;
        const int q    = gid & 8191;
        const int l    = q >> 6;
        const int d    = (q >> 5) & 1;
        const int r    = (q & 31) << 2;
        const float4 w = *(const float4*)(mid + (size_t)site * 32768 + l * 256 + d * 128 + r);
        uint32_t h01, h23, l01, l23;
        split4(w, h01, h23, l01, l23);
        const int khalf = r >> 6, rcol = r & 63;
        const size_t base = (size_t)site * 131072 + (size_t)khalf * 65536
                          + (size_t)d * 32768 + (size_t)l * 128
                          + (uint32_t)((((rcol >> 3) ^ (l & 7)) & 7) << 4)
                          + (uint32_t)((r & 7) << 1);
        *(uint2*)((char*)g_A + base)         = make_uint2(h01, h23);
        *(uint2*)((char*)g_A + base + 16384) = make_uint2(l01, l23);
    } else {
        const int b = blockIdx.x - 8128;
        const int n = threadIdx.x;
        const float v = x[b * NSITES + n];
        float mn = v, mx = v;
        #pragma unroll
        for (int off = 16; off > 0; off >>= 1) {
            mn = fminf(mn, __shfl_xor_sync(0xffffffffu, mn, off));
            mx = fmaxf(mx, __shfl_xor_sync(0xffffffffu, mx, off));
        }
        __shared__ float smn[8], smx[8];
        const int w = n >> 5, lane = n & 31;
        if (lane == 0) { smn[w] = mn; smx[w] = mx; }
        __syncthreads();
        mn = smn[0]; mx = smx[0];
        #pragma unroll
        for (int i = 1; i < 8; i++) { mn = fminf(mn, smn[i]); mx = fmaxf(mx, smx[i]); }
        const float ang = 1.57079632679489662f * (v - mn) / (mx - mn + 1e-6f);
        g_phiC[n * BATCH + b] = cosf(ang);
        g_phiS[n * BATCH + b] = sinf(ang);
    }
}

// ---------------------------------------------------------------------------
// Kernel 2: two independent 32-sample chains per CTA, fragment-pipelined MMAs.
// ---------------------------------------------------------------------------
extern __shared__ char smem_raw[];

__device__ __forceinline__ const char* half_src(int g) {
    const int site = MIDSITES - 1 - (g >> 1);
    return (const char*)g_A + (size_t)site * 131072 + (size_t)(g & 1) * 65536;
}

struct HalfFrag {
    uint32_t ah0[4], ah1[4], al0[4], al1[4];   // A fragments, g0
    uint32_t ch0[4], ch1[4], cl0[4], cl1[4];   // A fragments, g1
    uint32_t bh[4][2], bl[4][2];               // B fragments (shared)
};

__device__ __forceinline__ void ld_half(HalfFrag& f, uint32_t abuf, int st, int kh,
                                        uint32_t bh0, uint32_t bh1,
                                        int cA, int r7a) {
    const uint32_t kb = (uint32_t)((kh + st * 16) * 64);
    uint32_t q[4];
    ldsm4t(q, bh0 + kb);
    f.bh[0][0]=q[0]; f.bh[0][1]=q[1]; f.bh[1][0]=q[2]; f.bh[1][1]=q[3];
    ldsm4t(q, bh1 + kb);
    f.bh[2][0]=q[0]; f.bh[2][1]=q[1]; f.bh[3][0]=q[2]; f.bh[3][1]=q[3];
    ldsm4t(q, bh0 + kb + 16384);
    f.bl[0][0]=q[0]; f.bl[0][1]=q[1]; f.bl[1][0]=q[2]; f.bl[1][1]=q[3];
    ldsm4t(q, bh1 + kb + 16384);
    f.bl[2][0]=q[0]; f.bl[2][1]=q[1]; f.bl[3][0]=q[2]; f.bl[3][1]=q[3];

    const uint32_t tA = (uint32_t)((((2 * st + cA) ^ r7a) & 7) << 4);
    ldsm4(f.ah0, abuf + tA);
    ldsm4(f.ah1, abuf + tA + 2048);
    ldsm4(f.al0, abuf + tA + 16384);
    ldsm4(f.al1, abuf + tA + 18432);
    ldsm4(f.ch0, abuf + tA + 32768);
    ldsm4(f.ch1, abuf + tA + 34816);
    ldsm4(f.cl0, abuf + tA + 49152);
    ldsm4(f.cl1, abuf + tA + 51200);
}

__device__ __forceinline__ void do_khalf(
        uint32_t abuf, int kh, uint32_t bh0, uint32_t bh1,
        int cA, int r7a, float acc0[2][4][4], float acc1[2][4][4]) {
    HalfFrag F[2];
    ld_half(F[0], abuf, 0, kh, bh0, bh1, cA, r7a);
    #pragma unroll
    for (int st = 0; st < 4; st++) {
        if (st < 3)
            ld_half(F[(st + 1) & 1], abuf, st + 1, kh, bh0, bh1, cA, r7a);
        HalfFrag& f = F[st & 1];
        mma_group(acc0, f.ah0, f.ah1, f.al0, f.al1, f.bh, f.bl);
        mma_group(acc1, f.ch0, f.ch1, f.cl0, f.cl1, f.bh, f.bl);
    }
}

__global__ __launch_bounds__(NTHREADS, 1)
void mps_mma(const float* __restrict__ first,
             const float* __restrict__ last,
             const float* __restrict__ wlin,
             const float* __restrict__ blin,
             float* __restrict__ out) {
    const uint32_t sbase = (uint32_t)__cvta_generic_to_shared(smem_raw);
    const int tid  = threadIdx.x;
    const int wid  = tid >> 5, lane = tid & 31;
    const int grp  = wid >> 2;                 // 0: samples 0-31, 1: 32-63
    const int wm   = wid & 3;
    const int b0   = blockIdx.x * TSS;
    const int m_base = wm * 32;

    // A ldmatrix lane consts
    const int rowA = m_base + (lane & 15);
    const int cA   = lane >> 4;
    const int r7a  = rowA & 7;
    const uint32_t aoff = (uint32_t)(rowA * 128);

    // B ldmatrix.trans lane consts ([k 128][32 s] per group, 64B rows)
    const uint32_t grpB = sbase + OFF_BH + grp * 8192;
    const int kofsB = lane & 15;
    const int sg8   = (lane >> 4) << 3;        // 0 or 8
    const int chm   = (kofsB >> 1) & 3;
    const uint32_t bh0 = grpB + kofsB * 64 + (uint32_t)((((sg8 >> 3)       ^ chm) & 3) << 4);
    const uint32_t bh1 = grpB + kofsB * 64 + (uint32_t)(((((16 + sg8) >> 3) ^ chm) & 3) << 4);

    // epilogue lane consts
    const int rr = lane >> 2, cq = (lane & 3) * 2;
    char* gBh = smem_raw + OFF_BH + grp * 8192;
    char* gBl = gBh + 16384;

    const uint32_t fullb  = sbase + OFF_MB;
    const uint32_t emptyb = sbase + OFF_MB + 24;
    const uint32_t stgb   = sbase + OFF_MB + 48;

    if (tid < 3)        MBARRIER_INIT(fullb + tid * 8, 1);
    else if (tid < 6)   MBARRIER_INIT(emptyb + (tid - 3) * 8, 2);
    else if (tid == 6)  MBARRIER_INIT(stgb, 1);
    __syncthreads();

    if (tid == 0) {
        #pragma unroll
        for (int g = 0; g < 3; g++) {
            MBARRIER_EXPECT_TX(fullb + g * 8, 65536);
            BULK_CP(sbase + OFF_RING + g * 65536, half_src(g), 65536, fullb + g * 8);
        }
    }

    // initial B = last ⊙ phi[255] (per group, [k=r][s])
    {
        const int g_ = tid >> 7, r = tid & 127;
        char* bh_ = smem_raw + OFF_BH + g_ * 8192;
        char* bl_ = bh_ + 16384;
        const float l0 = last[2 * r], l1 = last[2 * r + 1];
        const float* pC = g_phiC + (size_t)(NSITES - 1) * BATCH + b0 + g_ * 32;
        const float* pS = g_phiS + (size_t)(NSITES - 1) * BATCH + b0 + g_ * 32;
        const int cm = (r >> 1) & 3;
        #pragma unroll
        for (int s = 0; s < 32; s += 2) {
            const float v0 = l0 * pC[s]     + l1 * pS[s];
            const float v1 = l0 * pC[s + 1] + l1 * pS[s + 1];
            uint32_t hh, ll;
            split2(v0, v1, hh, ll);
            const uint32_t o = (uint32_t)(r * 64 + ((((s >> 3) ^ cm) & 3) << 4)
                                          + ((s & 7) << 1));
            *(uint32_t*)(bh_ + o) = hh;
            *(uint32_t*)(bl_ + o) = ll;
        }
    }
    __syncthreads();

    if (grp == 1) MBAR_WAIT(stgb, 0);     // stagger: G1 starts after G0's first k-half

    for (int it = 0; it < MIDSITES; ++it) {
        const int i = MIDSITES - 1 - it;
        const bool last_it = (it == MIDSITES - 1);

        // prefetch phi[site i+1] (epilogue combine)
        float2 pc[4], ps[4];
        {
            const size_t pb = (size_t)(i + 1) * BATCH + b0 + grp * 32 + cq;
            #pragma unroll
            for (int ni = 0; ni < 4; ni++) {
                pc[ni] = *(const float2*)&g_phiC[pb + 8 * ni];
                ps[ni] = *(const float2*)&g_phiS[pb + 8 * ni];
            }
        }

        float acc0[2][4][4], acc1[2][4][4];
        #pragma unroll
        for (int mi = 0; mi < 2; mi++)
            #pragma unroll
            for (int ni = 0; ni < 4; ni++)
                #pragma unroll
                for (int e = 0; e < 4; e++) { acc0[mi][ni][e] = 0.0f; acc1[mi][ni][e] = 0.0f; }

        #pragma unroll
        for (int h = 0; h < 2; h++) {
            const int g    = 2 * it + h;
            const int slot = g % 3;
            const int par  = (g / 3) & 1;
            MBAR_WAIT(fullb + slot * 8, par);
            do_khalf(sbase + OFF_RING + slot * 65536 + aoff, h * 64,
                     bh0, bh1, cA, r7a, acc0, acc1);
            BARG();
            if ((tid & 127) == 0) {
                MBARRIER_ARRIVE(emptyb + slot * 8);
                if (grp == 1 && g < 505) {        // lagging group refills
                    MBAR_WAIT(emptyb + slot * 8, par);
                    MBARRIER_EXPECT_TX(fullb + slot * 8, 65536);
                    BULK_CP(sbase + OFF_RING + slot * 65536, half_src(g + 3),
                            65536, fullb + slot * 8);
                }
            }
            if (it == 0 && h == 0 && tid == 0) MBARRIER_ARRIVE(stgb);
        }

        if (!last_it) {
            // fused epilogue: right = c*D0 + s*D1 -> own next B (k-major)
            #pragma unroll
            for (int ni = 0; ni < 4; ni++) {
                const float cx = pc[ni].x, cy = pc[ni].y;
                const float sx = ps[ni].x, sy = ps[ni].y;
                #pragma unroll
                for (int mi = 0; mi < 2; mi++) {
                    const int r = m_base + 16 * mi + rr;
                    const float v0 = cx * acc0[mi][ni][0] + sx * acc1[mi][ni][0];
                    const float v1 = cy * acc0[mi][ni][1] + sy * acc1[mi][ni][1];
                    const float v2 = cx * acc0[mi][ni][2] + sx * acc1[mi][ni][2];
                    const float v3 = cy * acc0[mi][ni][3] + sy * acc1[mi][ni][3];
                    const uint32_t o = (uint32_t)(r * 64
                                     + (((ni ^ ((r >> 1) & 3)) & 3) << 4) + (cq << 1));
                    uint32_t hh, ll;
                    split2(v0, v1, hh, ll);
                    *(uint32_t*)(gBh + o) = hh;
                    *(uint32_t*)(gBl + o) = ll;
                    split2(v2, v3, hh, ll);
                    *(uint32_t*)(gBh + o + 512) = hh;   // r+8: same chunk, +8 rows
                    *(uint32_t*)(gBl + o + 512) = ll;
                }
            }
            BARG();   // own B ready for next site
        } else {
            // final head from fragments: scalar_s = sum_l L0(l,s) * right0(l,s)
            float2 c0v[4], s0v[4];
            const size_t hb = (size_t)b0 + grp * 32 + cq;
            #pragma unroll
            for (int ni = 0; ni < 4; ni++) {
                c0v[ni] = *(const float2*)&g_phiC[hb + 8 * ni];
                s0v[ni] = *(const float2*)&g_phiS[hb + 8 * ni];
            }
            float fA[2][2], fB[2][2];
            #pragma unroll
            for (int mi = 0; mi < 2; mi++) {
                const int l0 = m_base + 16 * mi + rr;
                fA[mi][0] = first[l0];      fB[mi][0] = first[DIM + l0];
                fA[mi][1] = first[l0 + 8];  fB[mi][1] = first[DIM + l0 + 8];
            }
            float* scr = (float*)gBh;   // B dead after final MMA
            #pragma unroll
            for (int ni = 0; ni < 4; ni++) {
                float pe = 0.f, po = 0.f;
                const float cx = pc[ni].x, cy = pc[ni].y;
                const float sx = ps[ni].x, sy = ps[ni].y;
                const float Lc0 = c0v[ni].x, Lc1 = c0v[ni].y;
                const float Ls0 = s0v[ni].x, Ls1 = s0v[ni].y;
                #pragma unroll
                for (int mi = 0; mi < 2; mi++) {
                    const float r0 = cx * acc0[mi][ni][0] + sx * acc1[mi][ni][0];
                    const float r1 = cy * acc0[mi][ni][1] + sy * acc1[mi][ni][1];
                    const float r2 = cx * acc0[mi][ni][2] + sx * acc1[mi][ni][2];
                    const float r3 = cy * acc0[mi][ni][3] + sy * acc1[mi][ni][3];
                    const float L0e = fA[mi][0] * Lc0 + fB[mi][0] * Ls0;
                    const float L0o = fA[mi][0] * Lc1 + fB[mi][0] * Ls1;
                    const float L1e = fA[mi][1] * Lc0 + fB[mi][1] * Ls0;
                    const float L1o = fA[mi][1] * Lc1 + fB[mi][1] * Ls1;
                    pe += L0e * r0 + L1e * r2;
                    po += L0o * r1 + L1o * r3;
                }
                #pragma unroll
                for (int m = 4; m <= 16; m <<= 1) {
                    pe += __shfl_xor_sync(0xffffffffu, pe, m);
                    po += __shfl_xor_sync(0xffffffffu, po, m);
                }
                if (lane < 4) {
                    scr[wm * 32 + 8 * ni + cq]     = pe;
                    scr[wm * 32 + 8 * ni + cq + 1] = po;
                }
            }
            BARG();
            const int gt = tid & 127;
            if (gt < 32) {
                const float sc = scr[gt] + scr[32 + gt] + scr[64 + gt] + scr[96 + gt];
                const int samp = b0 + grp * 32 + gt;
                #pragma unroll
                for (int o = 0; o < NOUT; o++)
                    out[samp * NOUT + o] = fmaf(sc, wlin[o], blin[o]);
            }
        }
    }
}

// ---------------------------------------------------------------------------
extern "C" void kernel_launch(void* const* d_in, const int* in_sizes, int n_in,
                              void* d_out, int out_size) {
    const float* x     = (const float*)d_in[0];
    const float* first = (const float*)d_in[1];
    const float* mid   = (const float*)d_in[2];
    const float* last  = (const float*)d_in[3];
    const float* wlin  = (const float*)d_in[4];
    const float* blin  = (const float*)d_in[5];
    float* out = (float*)d_out;

    cudaFuncSetAttribute(mps_mma, cudaFuncAttributeMaxDynamicSharedMemorySize,
                         SMEM_TOTAL);

    prep<<<16320, 256>>>(x, mid);
    mps_mma<<<BATCH / TSS, NTHREADS, SMEM_TOTAL>>>(first, last, wlin, blin, out);
}